// round 10
// baseline (speedup 1.0000x reference)
#include <cuda_runtime.h>
#include <cstdint>

#define L0 32
#define DIM 288          // 32 + 96 + 160 (logical irreps dim)
#define XSTR 384         // lane-major si1 row stride: 32 lanes * 12 floats
#define NRBF 8
#define HID 64
#define NPATHS 7
#define WCOLS 224        // NPATHS * L0
#define NORM 0.25f       // 1/sqrt(16)
#define NMAX 50176
#define TILE_E 32
#define HSTR 68          // h_sm row stride
#define WSTR 228         // w_sm row stride

// Scratch (static device globals; no runtime allocation allowed)
__device__ float g_si1[(size_t)NMAX * XSTR];   // lane-major si1
__device__ float g_conv[(size_t)NMAX * DIM];
// Wr2 tf32, mma-fragment order, 2 k-steps packed per uint4
__device__ uint4 g_Bfrag4[28 * 4 * 32];

__device__ __forceinline__ unsigned cvt_tf32(float v) {
    unsigned r;
    asm("cvt.rna.tf32.f32 %0, %1;" : "=r"(r) : "f"(v));
    return r;
}

// ---------------------------------------------------------------------------
// Kernel 0: build tf32 fragment-ordered Wr2 (pre-scaled by NORM), k-pair packed
// (idempotent — reused as dummy to keep k_edge at launch idx 3 for ncu)
// ---------------------------------------------------------------------------
__global__ void k_prep(const float* __restrict__ Wr2)
{
    int ntg = blockIdx.x;
    int t = threadIdx.x;
    int kp = t >> 5;
    int lane = t & 31;
    int r4 = lane >> 2, c4 = lane & 3;
    int col = ntg * 8 + r4;
    int ks0 = 2 * kp, ks1 = 2 * kp + 1;
    uint4 b;
    b.x = cvt_tf32(Wr2[(ks0 * 8 + c4)     * WCOLS + col] * NORM);
    b.y = cvt_tf32(Wr2[(ks0 * 8 + c4 + 4) * WCOLS + col] * NORM);
    b.z = cvt_tf32(Wr2[(ks1 * 8 + c4)     * WCOLS + col] * NORM);
    b.w = cvt_tf32(Wr2[(ks1 * 8 + c4 + 4) * WCOLS + col] * NORM);
    g_Bfrag4[(ntg * 4 + kp) * 32 + lane] = b;
}

// ---------------------------------------------------------------------------
// Kernel 1: si1 = irreps_linear(nodes), written LANE-MAJOR; zeroes g_conv rows
// ---------------------------------------------------------------------------
__global__ void k_lin1(const float* __restrict__ x,
                       const float* __restrict__ W0,
                       const float* __restrict__ W1,
                       const float* __restrict__ W2,
                       float* __restrict__ y,
                       float* __restrict__ convz, int N)
{
    __shared__ float W0s[1024], W1s[1024], W2s[1024];
    __shared__ float xs[8][DIM];
    int t = threadIdx.x;
    for (int i = t; i < 1024; i += blockDim.x) { W0s[i]=W0[i]; W1s[i]=W1[i]; W2s[i]=W2[i]; }
    __syncthreads();

    int wid = t >> 5, j = t & 31;
    int nwarps = (blockDim.x >> 5) * gridDim.x;
    const float4 z = make_float4(0.f, 0.f, 0.f, 0.f);
    for (int n = blockIdx.x * 8 + wid; n < N; n += nwarps) {
        const float* xr = x + (size_t)n * DIM;
        #pragma unroll
        for (int q = 0; q < 9; q++) xs[wid][j + 32*q] = xr[j + 32*q];

        float4* cz = (float4*)(convz + (size_t)n * DIM);
        cz[j] = z; cz[j + 32] = z;
        if (j < 8) cz[j + 64] = z;
        __syncwarp();

        float y0 = 0.f;
        #pragma unroll
        for (int i = 0; i < 32; i++) y0 = fmaf(xs[wid][i], W0s[i*32+j], y0);

        float y1[3] = {0.f,0.f,0.f};
        #pragma unroll
        for (int i = 0; i < 32; i++) {
            float w = W1s[i*32+j];
            #pragma unroll
            for (int c = 0; c < 3; c++) y1[c] = fmaf(xs[wid][32+3*i+c], w, y1[c]);
        }
        float y2[5] = {0.f,0.f,0.f,0.f,0.f};
        #pragma unroll
        for (int i = 0; i < 32; i++) {
            float w = W2s[i*32+j];
            #pragma unroll
            for (int c = 0; c < 5; c++) y2[c] = fmaf(xs[wid][128+5*i+c], w, y2[c]);
        }
        float4* yv = (float4*)(y + (size_t)n * XSTR + j * 12);
        yv[0] = make_float4(y0, y1[0], y1[1], y1[2]);
        yv[1] = make_float4(y2[0], y2[1], y2[2], y2[3]);
        yv[2] = make_float4(y2[4], 0.f, 0.f, 0.f);
        __syncwarp();
    }
}

// ---------------------------------------------------------------------------
// Kernel 2: edge conv — 32-edge tiles, occupancy 4, tf32 MMA, red.v4
// ---------------------------------------------------------------------------
__device__ __forceinline__ void mma_tf32(float& d0, float& d1, float& d2, float& d3,
                                         unsigned a0, unsigned a1, unsigned a2, unsigned a3,
                                         unsigned b0, unsigned b1)
{
    asm("mma.sync.aligned.m16n8k8.row.col.f32.tf32.tf32.f32 "
        "{%0,%1,%2,%3}, {%4,%5,%6,%7}, {%8,%9}, {%0,%1,%2,%3};"
        : "+f"(d0), "+f"(d1), "+f"(d2), "+f"(d3)
        : "r"(a0), "r"(a1), "r"(a2), "r"(a3), "r"(b0), "r"(b1));
}

__device__ __forceinline__ void flush_acc(float* __restrict__ conv, int dstn,
                                          float* __restrict__ ms_stage, int j,
                                          float a0, const float* a1, const float* a2)
{
    ms_stage[j] = a0;
    #pragma unroll
    for (int c = 0; c < 3; c++) ms_stage[32 + 3*j + c] = a1[c];
    #pragma unroll
    for (int c = 0; c < 5; c++) ms_stage[128 + 5*j + c] = a2[c];
    __syncwarp();
    float* db = conv + (size_t)dstn * DIM;
    float4 v0 = *(float4*)&ms_stage[j * 4];
    asm volatile("red.global.add.v4.f32 [%0], {%1,%2,%3,%4};"
                 :: "l"(db + j*4), "f"(v0.x), "f"(v0.y), "f"(v0.z), "f"(v0.w) : "memory");
    float4 v1 = *(float4*)&ms_stage[(j + 32) * 4];
    asm volatile("red.global.add.v4.f32 [%0], {%1,%2,%3,%4};"
                 :: "l"(db + (j+32)*4), "f"(v1.x), "f"(v1.y), "f"(v1.z), "f"(v1.w) : "memory");
    if (j < 8) {
        float4 v2 = *(float4*)&ms_stage[(j + 64) * 4];
        asm volatile("red.global.add.v4.f32 [%0], {%1,%2,%3,%4};"
                     :: "l"(db + (j+64)*4), "f"(v2.x), "f"(v2.y), "f"(v2.z), "f"(v2.w) : "memory");
    }
    __syncwarp();
}

__global__ void __launch_bounds__(256, 4) k_edge(
    const float* __restrict__ si1, const float* __restrict__ pos,
    const int* __restrict__ edge_index,      // int32 (JAX x64 disabled)
    const float* __restrict__ Wr1, const float* __restrict__ br1,
    float* __restrict__ conv, int E)
{
    extern __shared__ float sm[];
    float* h_sm   = sm;                             // 32*68 = 2176 (tf32 bits)
    float* w_sm   = h_sm + TILE_E * HSTR;           // 32*228 = 7296
    float* rbf_sm = w_sm + TILE_E * WSTR;           // 8*32 = 256
    float* uy_sm  = rbf_sm + NRBF * TILE_E;         // 32*8 = 256
    int*   src_sm = (int*)(uy_sm + 8 * TILE_E);     // 32
    int*   dst_sm = src_sm + TILE_E;                // 32
    float* m_sm   = (float*)(dst_sm + TILE_E);      // 8*292 = 2336
    float* Wr1s   = m_sm + 8 * 292;                 // 512
    float* br1s   = Wr1s + NRBF * HID;              // 64

    int t = threadIdx.x;
    for (int i = t; i < NRBF * HID; i += 256) Wr1s[i] = Wr1[i];
    if (t < HID) br1s[t] = br1[t];
    __syncthreads();

    const int j  = t & 31;   // lane
    const int g  = t >> 5;   // warp id (8 warps)
    const int e1 = t & 31;   // phase-1b edge within tile
    const int q  = t >> 5;   // phase-1b k-group (0..7, 8 k's each) == g
    const int r4 = j >> 2;
    const int c4 = j & 3;
    const int mt = g & 1;    // phase-2 m16 tile
    const int nq = g >> 1;   // phase-2 n-quarter (56 cols = 7 n8-tiles)
    const float rbf_step = 5.0f / 7.0f;

    const uint4* Bfrag = g_Bfrag4;

    int ntiles = (E + TILE_E - 1) / TILE_E;
    for (int tile = blockIdx.x; tile < ntiles; tile += gridDim.x) {
        int base = tile * TILE_E;

        // -------- phase 1a: geometry, once per edge (warp 0) --------
        if (t < TILE_E) {
            int eg = base + t;
            if (eg < E) {
                int s = edge_index[eg];
                int d = edge_index[(size_t)E + eg];
                float rx = pos[s*3+0] - pos[d*3+0];
                float ry = pos[s*3+1] - pos[d*3+1];
                float rz = pos[s*3+2] - pos[d*3+2];
                float dd = sqrtf(fmaf(rx,rx, fmaf(ry,ry, rz*rz)) + 1e-12f);
                float inv = 1.f / dd;
                float ux = rx*inv, uy = ry*inv, uz = rz*inv;
                #pragma unroll
                for (int r = 0; r < 8; r++) {
                    float dr = dd - rbf_step * (float)r;
                    rbf_sm[r*TILE_E + t] = __expf(-dr * dr);
                }
                float4* uv = (float4*)&uy_sm[t * 8];
                uv[0] = make_float4(ux, uy, uz, ux*uy);
                uv[1] = make_float4(uy*uz, (3.f*uz*uz - 1.f) * 0.2886751345948129f,
                                    ux*uz, (ux*ux - uy*uy) * 0.5f);
                src_sm[t] = s;
                dst_sm[t] = d;
            } else {
                #pragma unroll
                for (int r = 0; r < 8; r++) rbf_sm[r*TILE_E + t] = 0.f;
                float4* uv = (float4*)&uy_sm[t * 8];
                uv[0] = make_float4(0.f,0.f,0.f,0.f);
                uv[1] = make_float4(0.f,0.f,0.f,0.f);
                src_sm[t] = 0; dst_sm[t] = 0;
            }
        }
        __syncthreads();

        // -------- phase 1b: hidden layer h (tf32); thread = (edge, 8 k's) ------
        {
            float rbf[8];
            #pragma unroll
            for (int r = 0; r < 8; r++) rbf[r] = rbf_sm[r*TILE_E + e1];

            float a[8];
            {
                const float4* bb = (const float4*)&br1s[q*8];
                float4 b0 = bb[0], b1 = bb[1];
                a[0]=b0.x; a[1]=b0.y; a[2]=b0.z; a[3]=b0.w;
                a[4]=b1.x; a[5]=b1.y; a[6]=b1.z; a[7]=b1.w;
            }
            #pragma unroll
            for (int r = 0; r < 8; r++) {
                const float4* wr = (const float4*)&Wr1s[r*HID + q*8];
                float4 w0 = wr[0], w1 = wr[1];
                float rr = rbf[r];
                a[0] = fmaf(rr, w0.x, a[0]); a[1] = fmaf(rr, w0.y, a[1]);
                a[2] = fmaf(rr, w0.z, a[2]); a[3] = fmaf(rr, w0.w, a[3]);
                a[4] = fmaf(rr, w1.x, a[4]); a[5] = fmaf(rr, w1.y, a[5]);
                a[6] = fmaf(rr, w1.z, a[6]); a[7] = fmaf(rr, w1.w, a[7]);
            }
            unsigned hx[8];
            #pragma unroll
            for (int m = 0; m < 8; m++)
                hx[m] = cvt_tf32(a[m] / (1.f + __expf(-a[m])));   // silu -> tf32
            *(uint4*)&h_sm[e1*HSTR + q*8]     = make_uint4(hx[0],hx[1],hx[2],hx[3]);
            *(uint4*)&h_sm[e1*HSTR + q*8 + 4] = make_uint4(hx[4],hx[5],hx[6],hx[7]);
        }
        __syncthreads();

        // -------- phase 2: w = h @ Wr2; warp = 1 m16 x 7 n8 tiles --------
        {
            float acc[7][4];
            #pragma unroll
            for (int nt = 0; nt < 7; nt++)
                #pragma unroll
                for (int i = 0; i < 4; i++) acc[nt][i] = 0.f;

            const int arow = mt*16 + r4;
            #pragma unroll
            for (int kp = 0; kp < 4; kp++) {
                unsigned af[2][4];
                #pragma unroll
                for (int ks = 0; ks < 2; ks++) {
                    int ko = kp*16 + ks*8;
                    af[ks][0] = __float_as_uint(h_sm[ arow    *HSTR + ko + c4    ]);
                    af[ks][1] = __float_as_uint(h_sm[(arow+8)*HSTR + ko + c4    ]);
                    af[ks][2] = __float_as_uint(h_sm[ arow    *HSTR + ko + c4 + 4]);
                    af[ks][3] = __float_as_uint(h_sm[(arow+8)*HSTR + ko + c4 + 4]);
                }
                #pragma unroll
                for (int nt = 0; nt < 7; nt++) {
                    int ntg = nq*7 + nt;
                    uint4 b = __ldg(&Bfrag[(ntg*4 + kp)*32 + j]);
                    mma_tf32(acc[nt][0], acc[nt][1], acc[nt][2], acc[nt][3],
                             af[0][0], af[0][1], af[0][2], af[0][3], b.x, b.y);
                    mma_tf32(acc[nt][0], acc[nt][1], acc[nt][2], acc[nt][3],
                             af[1][0], af[1][1], af[1][2], af[1][3], b.z, b.w);
                }
            }
            #pragma unroll
            for (int nt = 0; nt < 7; nt++) {
                int col = nq*56 + nt*8 + 2*c4;
                int row = mt*16 + r4;
                *(float2*)&w_sm[ row    *WSTR + col] = make_float2(acc[nt][0], acc[nt][1]);
                *(float2*)&w_sm[(row+8)*WSTR + col] = make_float2(acc[nt][2], acc[nt][3]);
            }
        }
        __syncthreads();

        // -------- phase 3: lane-major direct gathers, compute, red.v4 ----------
        {
            const int ebase = g * 4;
            int nvalid = E - base - ebase;
            nvalid = nvalid < 0 ? 0 : (nvalid > 4 ? 4 : nvalid);
            if (nvalid > 0) {
                float* ms_stage = m_sm + g * 292;

                const float4* xr = (const float4*)(si1 + (size_t)src_sm[ebase] * XSTR + j*12);
                float4 pA = xr[0], pB = xr[1], pC = xr[2];

                #pragma unroll
                for (int es = 0; es < 4; es++) {
                    if (es < nvalid) {
                        float4 A = pA, B = pB, C = pC;
                        if (es + 1 < nvalid) {
                            const float4* nx = (const float4*)(si1 + (size_t)src_sm[ebase+es+1] * XSTR + j*12);
                            pA = nx[0]; pB = nx[1]; pC = nx[2];
                        }
                        int e = ebase + es;
                        float w[7];
                        #pragma unroll
                        for (int p = 0; p < 7; p++) w[p] = w_sm[e*WSTR + p*32 + j];

                        float4 uy0 = *(float4*)&uy_sm[e*8];
                        float4 uy1 = *(float4*)&uy_sm[e*8 + 4];

                        float x0 = A.x;
                        float x1v[3] = {A.y, A.z, A.w};
                        float x2v[5] = {B.x, B.y, B.z, B.w, C.x};

                        float t1 = fmaf(x1v[0], uy0.x, fmaf(x1v[1], uy0.y, x1v[2]*uy0.z));
                        float t2 = x2v[0]*uy0.w;
                        t2 = fmaf(x2v[1], uy1.x, t2);
                        t2 = fmaf(x2v[2], uy1.y, t2);
                        t2 = fmaf(x2v[3], uy1.z, t2);
                        t2 = fmaf(x2v[4], uy1.w, t2);

                        float m0 = fmaf(w[0], x0, fmaf(w[4], t1, w[6]*t2));
                        float a3 = w[3] * x0;
                        float a5 = w[5] * x0;
                        float m1[3], m2[5];
                        m1[0] = fmaf(w[1], x1v[0], a3*uy0.x);
                        m1[1] = fmaf(w[1], x1v[1], a3*uy0.y);
                        m1[2] = fmaf(w[1], x1v[2], a3*uy0.z);
                        m2[0] = fmaf(w[2], x2v[0], a5*uy0.w);
                        m2[1] = fmaf(w[2], x2v[1], a5*uy1.x);
                        m2[2] = fmaf(w[2], x2v[2], a5*uy1.y);
                        m2[3] = fmaf(w[2], x2v[3], a5*uy1.z);
                        m2[4] = fmaf(w[2], x2v[4], a5*uy1.w);

                        flush_acc(conv, dst_sm[e], ms_stage, j, m0, m1, m2);
                    }
                }
            }
        }
        __syncthreads();
    }
}

// ---------------------------------------------------------------------------
// Kernel 3: out = gate(nodes + irreps_linear(conv))
// ---------------------------------------------------------------------------
__global__ void k_lin2_gate(const float* __restrict__ conv,
                            const float* __restrict__ nodes,
                            const float* __restrict__ W0,
                            const float* __restrict__ W1,
                            const float* __restrict__ W2,
                            const float* __restrict__ Wg,
                            float* __restrict__ out, int N)
{
    __shared__ float W0s[1024], W1s[1024], W2s[1024], Wgs[2048];
    __shared__ float xs[8][DIM];
    __shared__ float m0s[8][32];
    int t = threadIdx.x;
    for (int i = t; i < 1024; i += blockDim.x) { W0s[i]=W0[i]; W1s[i]=W1[i]; W2s[i]=W2[i]; }
    for (int i = t; i < 2048; i += blockDim.x) Wgs[i] = Wg[i];
    __syncthreads();

    int wid = t >> 5, j = t & 31;
    int nwarps = (blockDim.x >> 5) * gridDim.x;
    for (int n = blockIdx.x * 8 + wid; n < N; n += nwarps) {
        const float* cr = conv + (size_t)n * DIM;
        const float* nr = nodes + (size_t)n * DIM;
        #pragma unroll
        for (int q = 0; q < 9; q++) xs[wid][j + 32*q] = cr[j + 32*q];
        __syncwarp();

        float y0 = nr[j];
        #pragma unroll
        for (int i = 0; i < 32; i++) y0 = fmaf(xs[wid][i], W0s[i*32+j], y0);
        m0s[wid][j] = y0;
        __syncwarp();

        float ga = 0.f, gb = 0.f;
        #pragma unroll
        for (int i = 0; i < 32; i++) {
            float mi = m0s[wid][i];
            ga = fmaf(mi, Wgs[i*64 + j],      ga);
            gb = fmaf(mi, Wgs[i*64 + 32 + j], gb);
        }
        ga = 1.f / (1.f + __expf(-ga));
        gb = 1.f / (1.f + __expf(-gb));

        float y1[3];
        #pragma unroll
        for (int c = 0; c < 3; c++) y1[c] = nr[32 + 3*j + c];
        #pragma unroll
        for (int i = 0; i < 32; i++) {
            float w = W1s[i*32+j];
            #pragma unroll
            for (int c = 0; c < 3; c++) y1[c] = fmaf(xs[wid][32+3*i+c], w, y1[c]);
        }
        float y2[5];
        #pragma unroll
        for (int c = 0; c < 5; c++) y2[c] = nr[128 + 5*j + c];
        #pragma unroll
        for (int i = 0; i < 32; i++) {
            float w = W2s[i*32+j];
            #pragma unroll
            for (int c = 0; c < 5; c++) y2[c] = fmaf(xs[wid][128+5*i+c], w, y2[c]);
        }

        float* yr = out + (size_t)n * DIM;
        yr[j] = y0 / (1.f + __expf(-y0));     // silu
        #pragma unroll
        for (int c = 0; c < 3; c++) yr[32 + 3*j + c] = y1[c] * ga;
        #pragma unroll
        for (int c = 0; c < 5; c++) yr[128 + 5*j + c] = y2[c] * gb;
        __syncwarp();
    }
}

// ---------------------------------------------------------------------------
extern "C" void kernel_launch(void* const* d_in, const int* in_sizes, int n_in,
                              void* d_out, int out_size)
{
    const float* nodes = (const float*)d_in[0];
    const float* pos   = (const float*)d_in[1];
    const float* W0    = (const float*)d_in[2];
    const float* W1    = (const float*)d_in[3];
    const float* W2    = (const float*)d_in[4];
    const float* Wr1   = (const float*)d_in[5];
    const float* br1   = (const float*)d_in[6];
    const float* Wr2   = (const float*)d_in[7];
    const float* Wg    = (const float*)d_in[8];
    const int* edge_index = (const int*)d_in[10];   // int32: JAX x64 disabled
    float* out = (float*)d_out;

    int N = in_sizes[0] / DIM;
    int E = in_sizes[10] / 2;

    float *si1p, *convp;
    cudaGetSymbolAddress((void**)&si1p, g_si1);
    cudaGetSymbolAddress((void**)&convp, g_conv);

    int nblocks = (N + 7) / 8;
    if (nblocks > 2048) nblocks = 2048;

    k_prep<<<28, 128>>>(Wr2);                                       // kernel 0
    k_lin1<<<nblocks, 256>>>(nodes, W0, W1, W2, si1p, convp, N);    // kernel 1
    k_prep<<<28, 128>>>(Wr2);   // idempotent dummy — keeps k_edge at idx 3

    // dynamic shared floats: h 2176 + w 7296 + rbf 256 + uy 256 + idx 64
    //   + m 2336 + Wr1 512 + br1 64 = 12960 floats = 51840 B -> occupancy 4
    const int SMEM_FLOATS = TILE_E*HSTR + TILE_E*WSTR + NRBF*TILE_E + 8*TILE_E
                          + 2*TILE_E + 8*292 + NRBF*HID + HID;
    const int SMEM = SMEM_FLOATS * 4;
    cudaFuncSetAttribute(k_edge, cudaFuncAttributeMaxDynamicSharedMemorySize, SMEM);
    k_edge<<<1184, 256, SMEM>>>(si1p, pos, edge_index, Wr1, br1, convp, E);  // kernel 3

    k_lin2_gate<<<nblocks, 256>>>(convp, nodes, W0, W1, W2, Wg, out, N);    // kernel 4
}

// round 11
// speedup vs baseline: 1.1096x; 1.1096x over previous
#include <cuda_runtime.h>
#include <cstdint>

#define L0 32
#define DIM 288          // logical irreps dim; SoA rows are also 288 floats
#define XSTR 288         // SoA row stride: [4f/lane x32][4f/lane x32][1f/lane x32]
#define NRBF 8
#define HID 64
#define NPATHS 7
#define WCOLS 224        // NPATHS * L0
#define NORM 0.25f       // 1/sqrt(16)
#define NMAX 50176
#define TILE_E 64
#define HSTR 68          // h_sm row stride
#define WSTR 228         // w_sm row stride

// Scratch (static device globals; no runtime allocation allowed)
__device__ float g_si1[(size_t)NMAX * XSTR];   // SoA si1
__device__ float g_conv[(size_t)NMAX * XSTR];  // SoA conv accumulator
// Wr2 tf32, mma-fragment order, 2 k-steps packed per uint4
__device__ uint4 g_Bfrag4[28 * 4 * 32];

__device__ __forceinline__ unsigned cvt_tf32(float v) {
    unsigned r;
    asm("cvt.rna.tf32.f32 %0, %1;" : "=r"(r) : "f"(v));
    return r;
}

// ---------------------------------------------------------------------------
// Kernel 0: build tf32 fragment-ordered Wr2 (pre-scaled by NORM), k-pair packed
// (idempotent — reused as dummy to keep k_edge at launch idx 3 for ncu)
// ---------------------------------------------------------------------------
__global__ void k_prep(const float* __restrict__ Wr2)
{
    int ntg = blockIdx.x;
    int t = threadIdx.x;
    int kp = t >> 5;
    int lane = t & 31;
    int r4 = lane >> 2, c4 = lane & 3;
    int col = ntg * 8 + r4;
    int ks0 = 2 * kp, ks1 = 2 * kp + 1;
    uint4 b;
    b.x = cvt_tf32(Wr2[(ks0 * 8 + c4)     * WCOLS + col] * NORM);
    b.y = cvt_tf32(Wr2[(ks0 * 8 + c4 + 4) * WCOLS + col] * NORM);
    b.z = cvt_tf32(Wr2[(ks1 * 8 + c4)     * WCOLS + col] * NORM);
    b.w = cvt_tf32(Wr2[(ks1 * 8 + c4 + 4) * WCOLS + col] * NORM);
    g_Bfrag4[(ntg * 4 + kp) * 32 + lane] = b;
}

// ---------------------------------------------------------------------------
// Kernel 1: si1 = irreps_linear(nodes), written SoA; zeroes g_conv rows
// ---------------------------------------------------------------------------
__global__ void k_lin1(const float* __restrict__ x,
                       const float* __restrict__ W0,
                       const float* __restrict__ W1,
                       const float* __restrict__ W2,
                       float* __restrict__ y,
                       float* __restrict__ convz, int N)
{
    __shared__ float W0s[1024], W1s[1024], W2s[1024];
    __shared__ float xs[8][DIM];
    int t = threadIdx.x;
    for (int i = t; i < 1024; i += blockDim.x) { W0s[i]=W0[i]; W1s[i]=W1[i]; W2s[i]=W2[i]; }
    __syncthreads();

    int wid = t >> 5, j = t & 31;
    int nwarps = (blockDim.x >> 5) * gridDim.x;
    const float4 z = make_float4(0.f, 0.f, 0.f, 0.f);
    for (int n = blockIdx.x * 8 + wid; n < N; n += nwarps) {
        const float* xr = x + (size_t)n * DIM;
        #pragma unroll
        for (int q = 0; q < 9; q++) xs[wid][j + 32*q] = xr[j + 32*q];

        float4* cz = (float4*)(convz + (size_t)n * XSTR);
        cz[j] = z; cz[j + 32] = z;
        if (j < 8) cz[j + 64] = z;
        __syncwarp();

        float y0 = 0.f;
        #pragma unroll
        for (int i = 0; i < 32; i++) y0 = fmaf(xs[wid][i], W0s[i*32+j], y0);

        float y1[3] = {0.f,0.f,0.f};
        #pragma unroll
        for (int i = 0; i < 32; i++) {
            float w = W1s[i*32+j];
            #pragma unroll
            for (int c = 0; c < 3; c++) y1[c] = fmaf(xs[wid][32+3*i+c], w, y1[c]);
        }
        float y2[5] = {0.f,0.f,0.f,0.f,0.f};
        #pragma unroll
        for (int i = 0; i < 32; i++) {
            float w = W2s[i*32+j];
            #pragma unroll
            for (int c = 0; c < 5; c++) y2[c] = fmaf(xs[wid][128+5*i+c], w, y2[c]);
        }
        // SoA write: A-block float4, B-block float4, C-block scalar
        float* yr = y + (size_t)n * XSTR;
        ((float4*)yr)[j]      = make_float4(y0, y1[0], y1[1], y1[2]);
        ((float4*)yr)[32 + j] = make_float4(y2[0], y2[1], y2[2], y2[3]);
        yr[256 + j] = y2[4];
        __syncwarp();
    }
}

// ---------------------------------------------------------------------------
// Kernel 2: edge conv — SoA gathers + tf32 MMA + direct SoA red (no staging)
// ---------------------------------------------------------------------------
__device__ __forceinline__ void mma_tf32(float& d0, float& d1, float& d2, float& d3,
                                         unsigned a0, unsigned a1, unsigned a2, unsigned a3,
                                         unsigned b0, unsigned b1)
{
    asm("mma.sync.aligned.m16n8k8.row.col.f32.tf32.tf32.f32 "
        "{%0,%1,%2,%3}, {%4,%5,%6,%7}, {%8,%9}, {%0,%1,%2,%3};"
        : "+f"(d0), "+f"(d1), "+f"(d2), "+f"(d3)
        : "r"(a0), "r"(a1), "r"(a2), "r"(a3), "r"(b0), "r"(b1));
}

__global__ void __launch_bounds__(256, 2) k_edge(
    const float* __restrict__ si1, const float* __restrict__ pos,
    const int* __restrict__ edge_index,      // int32 (JAX x64 disabled)
    const float* __restrict__ Wr1, const float* __restrict__ br1,
    float* __restrict__ conv, int E)
{
    extern __shared__ float sm[];
    float* h_sm   = sm;                             // 64*68 = 4352 (tf32, permuted k)
    float* w_sm   = h_sm + TILE_E * HSTR;           // 64*228 = 14592
    float* rbf_sm = w_sm + TILE_E * WSTR;           // 8*64 = 512
    float* uy_sm  = rbf_sm + NRBF * TILE_E;         // 64*8 = 512
    int*   src_sm = (int*)(uy_sm + 8 * TILE_E);     // 64
    int*   dst_sm = src_sm + TILE_E;                // 64
    float* Wr1s   = (float*)(dst_sm + TILE_E);      // 512
    float* br1s   = Wr1s + NRBF * HID;              // 64

    int t = threadIdx.x;
    for (int i = t; i < NRBF * HID; i += 256) Wr1s[i] = Wr1[i];
    if (t < HID) br1s[t] = br1[t];
    __syncthreads();

    const int j  = t & 31;   // lane
    const int g  = t >> 5;   // warp id (8 warps)
    const int e1 = t & 63;   // phase-1b edge within tile
    const int q  = t >> 6;   // phase-1b k-group (0..3), 16 k's each
    const int r4 = j >> 2;
    const int c4 = j & 3;
    const int msb = g & 1;   // phase-2 m-slab (32 edges)
    const int nq = g >> 1;   // phase-2 n-quarter (56 cols = 7 n8-tiles)
    const float rbf_step = 5.0f / 7.0f;

    const uint4* Bfrag = g_Bfrag4;

    int ntiles = (E + TILE_E - 1) / TILE_E;
    for (int tile = blockIdx.x; tile < ntiles; tile += gridDim.x) {
        int base = tile * TILE_E;

        // -------- phase 1a: geometry, once per edge (threads 0..63) --------
        if (t < TILE_E) {
            int eg = base + t;
            if (eg < E) {
                int s = edge_index[eg];
                int d = edge_index[(size_t)E + eg];
                float rx = pos[s*3+0] - pos[d*3+0];
                float ry = pos[s*3+1] - pos[d*3+1];
                float rz = pos[s*3+2] - pos[d*3+2];
                float dd = sqrtf(fmaf(rx,rx, fmaf(ry,ry, rz*rz)) + 1e-12f);
                float inv = 1.f / dd;
                float ux = rx*inv, uy = ry*inv, uz = rz*inv;
                #pragma unroll
                for (int r = 0; r < 8; r++) {
                    float dr = dd - rbf_step * (float)r;
                    rbf_sm[r*TILE_E + t] = __expf(-dr * dr);
                }
                float4* uv = (float4*)&uy_sm[t * 8];
                uv[0] = make_float4(ux, uy, uz, ux*uy);
                uv[1] = make_float4(uy*uz, (3.f*uz*uz - 1.f) * 0.2886751345948129f,
                                    ux*uz, (ux*ux - uy*uy) * 0.5f);
                src_sm[t] = s;
                dst_sm[t] = d;
            } else {
                #pragma unroll
                for (int r = 0; r < 8; r++) rbf_sm[r*TILE_E + t] = 0.f;
                float4* uv = (float4*)&uy_sm[t * 8];
                uv[0] = make_float4(0.f,0.f,0.f,0.f);
                uv[1] = make_float4(0.f,0.f,0.f,0.f);
                src_sm[t] = 0; dst_sm[t] = 0;
            }
        }
        __syncthreads();

        // -------- phase 1b: hidden layer h (tf32), vectorized, permuted-k pack --
        {
            float rbf[8];
            #pragma unroll
            for (int r = 0; r < 8; r++) rbf[r] = rbf_sm[r*TILE_E + e1];

            float a[16];
            {
                const float4* bb = (const float4*)&br1s[q*16];
                #pragma unroll
                for (int v = 0; v < 4; v++) {
                    float4 b4 = bb[v];
                    a[4*v+0]=b4.x; a[4*v+1]=b4.y; a[4*v+2]=b4.z; a[4*v+3]=b4.w;
                }
            }
            #pragma unroll
            for (int r = 0; r < 8; r++) {
                const float4* wr = (const float4*)&Wr1s[r*HID + q*16];
                float rr = rbf[r];
                #pragma unroll
                for (int v = 0; v < 4; v++) {
                    float4 w4 = wr[v];
                    a[4*v+0] = fmaf(rr, w4.x, a[4*v+0]);
                    a[4*v+1] = fmaf(rr, w4.y, a[4*v+1]);
                    a[4*v+2] = fmaf(rr, w4.z, a[4*v+2]);
                    a[4*v+3] = fmaf(rr, w4.w, a[4*v+3]);
                }
            }
            unsigned hx[16];
            #pragma unroll
            for (int m = 0; m < 16; m++)
                hx[m] = cvt_tf32(a[m] / (1.f + __expf(-a[m])));   // silu -> tf32

            // permuted-k pack: physical p holds hx[(p>>2) + 4*(p&3)]
            #pragma unroll
            for (int v = 0; v < 4; v++) {
                uint4 pk = make_uint4(hx[(4*v+0)/4 + 4*((4*v+0)&3)],
                                      hx[(4*v+1)/4 + 4*((4*v+1)&3)],
                                      hx[(4*v+2)/4 + 4*((4*v+2)&3)],
                                      hx[(4*v+3)/4 + 4*((4*v+3)&3)]);
                *(uint4*)&h_sm[e1*HSTR + q*16 + 4*v] = pk;
            }
        }
        __syncthreads();

        // -------- phase 2: w = h @ Wr2, 2m x 4n split, LDS.128 A-frags --------
        {
            float acc[2][7][4];
            #pragma unroll
            for (int mt = 0; mt < 2; mt++)
                #pragma unroll
                for (int nt = 0; nt < 7; nt++)
                    #pragma unroll
                    for (int i = 0; i < 4; i++) acc[mt][nt][i] = 0.f;

            #pragma unroll
            for (int kp = 0; kp < 4; kp++) {
                uint4 va[2], vb[2];
                #pragma unroll
                for (int mt = 0; mt < 2; mt++) {
                    int arow = msb*32 + mt*16 + r4;
                    va[mt] = *(uint4*)&h_sm[ arow    *HSTR + kp*16 + c4*4];
                    vb[mt] = *(uint4*)&h_sm[(arow+8)*HSTR + kp*16 + c4*4];
                }
                #pragma unroll
                for (int nt = 0; nt < 7; nt++) {
                    int ntg = nq*7 + nt;
                    uint4 b = __ldg(&Bfrag[(ntg*4 + kp)*32 + j]);
                    #pragma unroll
                    for (int mt = 0; mt < 2; mt++) {
                        mma_tf32(acc[mt][nt][0], acc[mt][nt][1], acc[mt][nt][2], acc[mt][nt][3],
                                 va[mt].x, vb[mt].x, va[mt].y, vb[mt].y, b.x, b.y);
                        mma_tf32(acc[mt][nt][0], acc[mt][nt][1], acc[mt][nt][2], acc[mt][nt][3],
                                 va[mt].z, vb[mt].z, va[mt].w, vb[mt].w, b.z, b.w);
                    }
                }
            }
            #pragma unroll
            for (int mt = 0; mt < 2; mt++) {
                #pragma unroll
                for (int nt = 0; nt < 7; nt++) {
                    int col = nq*56 + nt*8 + 2*c4;
                    int row = msb*32 + mt*16 + r4;
                    *(float2*)&w_sm[ row    *WSTR + col] = make_float2(acc[mt][nt][0], acc[mt][nt][1]);
                    *(float2*)&w_sm[(row+8)*WSTR + col] = make_float2(acc[mt][nt][2], acc[mt][nt][3]);
                }
            }
        }
        __syncthreads();

        // -------- phase 3: SoA gathers, compute, direct SoA red (no staging) ----
        {
            const int ebase = g * 8;
            int nvalid = E - base - ebase;
            nvalid = nvalid < 0 ? 0 : (nvalid > 8 ? 8 : nvalid);
            if (nvalid > 0) {
                // prefetch edge 0: contiguous SoA loads
                const float* x0p = si1 + (size_t)src_sm[ebase] * XSTR;
                float4 pA = ((const float4*)x0p)[j];
                float4 pB = ((const float4*)x0p)[32 + j];
                float  pC = x0p[256 + j];

                #pragma unroll
                for (int es = 0; es < 8; es++) {
                    if (es < nvalid) {
                        float4 A = pA, B = pB;
                        float  C = pC;
                        if (es + 1 < nvalid) {
                            const float* nx = si1 + (size_t)src_sm[ebase+es+1] * XSTR;
                            pA = ((const float4*)nx)[j];
                            pB = ((const float4*)nx)[32 + j];
                            pC = nx[256 + j];
                        }
                        int e = ebase + es;
                        float w[7];
                        #pragma unroll
                        for (int p = 0; p < 7; p++) w[p] = w_sm[e*WSTR + p*32 + j];

                        float4 uy0 = *(float4*)&uy_sm[e*8];
                        float4 uy1 = *(float4*)&uy_sm[e*8 + 4];
                        // u = (uy0.x,y,z); Y2 = (uy0.w, uy1.x,y,z,w)

                        float x0 = A.x;
                        float x1v[3] = {A.y, A.z, A.w};
                        float x2v[5] = {B.x, B.y, B.z, B.w, C};

                        float t1 = fmaf(x1v[0], uy0.x, fmaf(x1v[1], uy0.y, x1v[2]*uy0.z));
                        float t2 = x2v[0]*uy0.w;
                        t2 = fmaf(x2v[1], uy1.x, t2);
                        t2 = fmaf(x2v[2], uy1.y, t2);
                        t2 = fmaf(x2v[3], uy1.z, t2);
                        t2 = fmaf(x2v[4], uy1.w, t2);

                        float m0 = fmaf(w[0], x0, fmaf(w[4], t1, w[6]*t2));
                        float a3 = w[3] * x0;
                        float a5 = w[5] * x0;
                        float m1x = fmaf(w[1], x1v[0], a3*uy0.x);
                        float m1y = fmaf(w[1], x1v[1], a3*uy0.y);
                        float m1z = fmaf(w[1], x1v[2], a3*uy0.z);
                        float m20 = fmaf(w[2], x2v[0], a5*uy0.w);
                        float m21 = fmaf(w[2], x2v[1], a5*uy1.x);
                        float m22 = fmaf(w[2], x2v[2], a5*uy1.y);
                        float m23 = fmaf(w[2], x2v[3], a5*uy1.z);
                        float m24 = fmaf(w[2], x2v[4], a5*uy1.w);

                        float* db = conv + (size_t)dst_sm[e] * XSTR;
                        asm volatile("red.global.add.v4.f32 [%0], {%1,%2,%3,%4};"
                                     :: "l"(db + j*4), "f"(m0), "f"(m1x), "f"(m1y), "f"(m1z)
                                     : "memory");
                        asm volatile("red.global.add.v4.f32 [%0], {%1,%2,%3,%4};"
                                     :: "l"(db + 128 + j*4), "f"(m20), "f"(m21), "f"(m22), "f"(m23)
                                     : "memory");
                        asm volatile("red.global.add.f32 [%0], %1;"
                                     :: "l"(db + 256 + j), "f"(m24) : "memory");
                    }
                }
            }
        }
        __syncthreads();
    }
}

// ---------------------------------------------------------------------------
// Kernel 3: out = gate(nodes + irreps_linear(conv))   (conv read as SoA)
// ---------------------------------------------------------------------------
__global__ void k_lin2_gate(const float* __restrict__ conv,
                            const float* __restrict__ nodes,
                            const float* __restrict__ W0,
                            const float* __restrict__ W1,
                            const float* __restrict__ W2,
                            const float* __restrict__ Wg,
                            float* __restrict__ out, int N)
{
    __shared__ float W0s[1024], W1s[1024], W2s[1024], Wgs[2048];
    __shared__ float xs[8][DIM];
    __shared__ float m0s[8][32];
    int t = threadIdx.x;
    for (int i = t; i < 1024; i += blockDim.x) { W0s[i]=W0[i]; W1s[i]=W1[i]; W2s[i]=W2[i]; }
    for (int i = t; i < 2048; i += blockDim.x) Wgs[i] = Wg[i];
    __syncthreads();

    int wid = t >> 5, j = t & 31;
    int nwarps = (blockDim.x >> 5) * gridDim.x;
    for (int n = blockIdx.x * 8 + wid; n < N; n += nwarps) {
        const float* cr = conv + (size_t)n * XSTR;
        const float* nr = nodes + (size_t)n * DIM;
        // SoA -> logical remap into shared
        {
            float4 cA = ((const float4*)cr)[j];
            float4 cB = ((const float4*)cr)[32 + j];
            float  cC = cr[256 + j];
            xs[wid][j] = cA.x;
            xs[wid][32 + 3*j + 0] = cA.y;
            xs[wid][32 + 3*j + 1] = cA.z;
            xs[wid][32 + 3*j + 2] = cA.w;
            xs[wid][128 + 5*j + 0] = cB.x;
            xs[wid][128 + 5*j + 1] = cB.y;
            xs[wid][128 + 5*j + 2] = cB.z;
            xs[wid][128 + 5*j + 3] = cB.w;
            xs[wid][128 + 5*j + 4] = cC;
        }
        __syncwarp();

        float y0 = nr[j];
        #pragma unroll
        for (int i = 0; i < 32; i++) y0 = fmaf(xs[wid][i], W0s[i*32+j], y0);
        m0s[wid][j] = y0;
        __syncwarp();

        float ga = 0.f, gb = 0.f;
        #pragma unroll
        for (int i = 0; i < 32; i++) {
            float mi = m0s[wid][i];
            ga = fmaf(mi, Wgs[i*64 + j],      ga);
            gb = fmaf(mi, Wgs[i*64 + 32 + j], gb);
        }
        ga = 1.f / (1.f + __expf(-ga));
        gb = 1.f / (1.f + __expf(-gb));

        float y1[3];
        #pragma unroll
        for (int c = 0; c < 3; c++) y1[c] = nr[32 + 3*j + c];
        #pragma unroll
        for (int i = 0; i < 32; i++) {
            float w = W1s[i*32+j];
            #pragma unroll
            for (int c = 0; c < 3; c++) y1[c] = fmaf(xs[wid][32+3*i+c], w, y1[c]);
        }
        float y2[5];
        #pragma unroll
        for (int c = 0; c < 5; c++) y2[c] = nr[128 + 5*j + c];
        #pragma unroll
        for (int i = 0; i < 32; i++) {
            float w = W2s[i*32+j];
            #pragma unroll
            for (int c = 0; c < 5; c++) y2[c] = fmaf(xs[wid][128+5*i+c], w, y2[c]);
        }

        float* yr = out + (size_t)n * DIM;
        yr[j] = y0 / (1.f + __expf(-y0));     // silu
        #pragma unroll
        for (int c = 0; c < 3; c++) yr[32 + 3*j + c] = y1[c] * ga;
        #pragma unroll
        for (int c = 0; c < 5; c++) yr[128 + 5*j + c] = y2[c] * gb;
        __syncwarp();
    }
}

// ---------------------------------------------------------------------------
extern "C" void kernel_launch(void* const* d_in, const int* in_sizes, int n_in,
                              void* d_out, int out_size)
{
    const float* nodes = (const float*)d_in[0];
    const float* pos   = (const float*)d_in[1];
    const float* W0    = (const float*)d_in[2];
    const float* W1    = (const float*)d_in[3];
    const float* W2    = (const float*)d_in[4];
    const float* Wr1   = (const float*)d_in[5];
    const float* br1   = (const float*)d_in[6];
    const float* Wr2   = (const float*)d_in[7];
    const float* Wg    = (const float*)d_in[8];
    const int* edge_index = (const int*)d_in[10];   // int32: JAX x64 disabled
    float* out = (float*)d_out;

    int N = in_sizes[0] / DIM;
    int E = in_sizes[10] / 2;

    float *si1p, *convp;
    cudaGetSymbolAddress((void**)&si1p, g_si1);
    cudaGetSymbolAddress((void**)&convp, g_conv);

    int nblocks = (N + 7) / 8;
    if (nblocks > 2048) nblocks = 2048;

    k_prep<<<28, 128>>>(Wr2);                                       // kernel 0
    k_lin1<<<nblocks, 256>>>(nodes, W0, W1, W2, si1p, convp, N);    // kernel 1
    k_prep<<<28, 128>>>(Wr2);   // idempotent dummy — keeps k_edge at idx 3

    // dynamic shared floats: h 4352 + w 14592 + rbf 512 + uy 512 + idx 128
    //   + Wr1 512 + br1 64 = 20672 floats = 82688 B -> occupancy 2
    const int SMEM_FLOATS = TILE_E*HSTR + TILE_E*WSTR + NRBF*TILE_E + 8*TILE_E
                          + 2*TILE_E + NRBF*HID + HID;
    const int SMEM = SMEM_FLOATS * 4;
    cudaFuncSetAttribute(k_edge, cudaFuncAttributeMaxDynamicSharedMemorySize, SMEM);
    k_edge<<<592, 256, SMEM>>>(si1p, pos, edge_index, Wr1, br1, convp, E);  // kernel 3

    k_lin2_gate<<<nblocks, 256>>>(convp, nodes, W0, W1, W2, Wg, out, N);    // kernel 4
}

// round 12
// speedup vs baseline: 1.5222x; 1.3718x over previous
#include <cuda_runtime.h>
#include <cuda_fp16.h>
#include <cstdint>

#define L0 32
#define DIM 288          // logical irreps dim
#define XSTR 288         // SoA row stride (si1: halves; conv: floats)
#define NRBF 8
#define HID 64
#define NPATHS 7
#define WCOLS 224        // NPATHS * L0
#define NORM 0.25f       // 1/sqrt(16)
#define NMAX 50176
#define TILE_E 64
#define HSTRH 72         // h_sm row stride in halves (conflict-free A LDS.32)
#define WSTRH 232        // w_sm row stride in halves

// Scratch (static device globals; no runtime allocation allowed)
__device__ __half g_si1h[(size_t)NMAX * XSTR];   // SoA si1, fp16
__device__ float  g_conv[(size_t)NMAX * XSTR];   // SoA conv accumulator, fp32
// Wr2 fp16, mma m16n8k16 fragment order; 2 k-steps packed per uint4
__device__ uint4 g_Bfrag16[28 * 2 * 32];

__device__ __forceinline__ unsigned pack_h2(float lo, float hi) {
    __half2 h = __floats2half2_rn(lo, hi);
    return *(unsigned*)&h;
}

// ---------------------------------------------------------------------------
// Kernel 0: build fp16 fragment-ordered Wr2 (pre-scaled by NORM)
// (idempotent — reused as dummy to keep k_edge at launch idx 3 for ncu)
// ---------------------------------------------------------------------------
__global__ void k_prep(const float* __restrict__ Wr2)
{
    int ntg = blockIdx.x;            // 0..27 (n-tile of 8 cols)
    int t = threadIdx.x;             // 64 threads: kd = t>>5 (k-step pair), lane
    int kd = t >> 5;
    int lane = t & 31;
    int col = ntg * 8 + (lane >> 2);
    int m4 = (lane & 3) * 2;
    int kb0 = (2*kd)     * 16 + m4;
    int kb1 = (2*kd + 1) * 16 + m4;
    uint4 b;
    b.x = pack_h2(Wr2[ kb0      * WCOLS + col] * NORM, Wr2[(kb0+1) * WCOLS + col] * NORM);
    b.y = pack_h2(Wr2[(kb0+8)   * WCOLS + col] * NORM, Wr2[(kb0+9) * WCOLS + col] * NORM);
    b.z = pack_h2(Wr2[ kb1      * WCOLS + col] * NORM, Wr2[(kb1+1) * WCOLS + col] * NORM);
    b.w = pack_h2(Wr2[(kb1+8)   * WCOLS + col] * NORM, Wr2[(kb1+9) * WCOLS + col] * NORM);
    g_Bfrag16[(ntg * 2 + kd) * 32 + lane] = b;
}

// ---------------------------------------------------------------------------
// Kernel 1: si1 = irreps_linear(nodes), written fp16 SoA; zeroes g_conv rows
// ---------------------------------------------------------------------------
__global__ void k_lin1(const float* __restrict__ x,
                       const float* __restrict__ W0,
                       const float* __restrict__ W1,
                       const float* __restrict__ W2,
                       __half* __restrict__ y,
                       float* __restrict__ convz, int N)
{
    __shared__ float W0s[1024], W1s[1024], W2s[1024];
    __shared__ float xs[8][DIM];
    int t = threadIdx.x;
    for (int i = t; i < 1024; i += blockDim.x) { W0s[i]=W0[i]; W1s[i]=W1[i]; W2s[i]=W2[i]; }
    __syncthreads();

    int wid = t >> 5, j = t & 31;
    int nwarps = (blockDim.x >> 5) * gridDim.x;
    const float4 z = make_float4(0.f, 0.f, 0.f, 0.f);
    for (int n = blockIdx.x * 8 + wid; n < N; n += nwarps) {
        const float* xr = x + (size_t)n * DIM;
        #pragma unroll
        for (int q = 0; q < 9; q++) xs[wid][j + 32*q] = xr[j + 32*q];

        float4* cz = (float4*)(convz + (size_t)n * XSTR);
        cz[j] = z; cz[j + 32] = z;
        if (j < 8) cz[j + 64] = z;
        __syncwarp();

        float y0 = 0.f;
        #pragma unroll
        for (int i = 0; i < 32; i++) y0 = fmaf(xs[wid][i], W0s[i*32+j], y0);

        float y1[3] = {0.f,0.f,0.f};
        #pragma unroll
        for (int i = 0; i < 32; i++) {
            float w = W1s[i*32+j];
            #pragma unroll
            for (int c = 0; c < 3; c++) y1[c] = fmaf(xs[wid][32+3*i+c], w, y1[c]);
        }
        float y2[5] = {0.f,0.f,0.f,0.f,0.f};
        #pragma unroll
        for (int i = 0; i < 32; i++) {
            float w = W2s[i*32+j];
            #pragma unroll
            for (int c = 0; c < 5; c++) y2[c] = fmaf(xs[wid][128+5*i+c], w, y2[c]);
        }
        // fp16 SoA write: 8 halves per lane (uint4) + 1 tail half
        __half* yr = y + (size_t)n * XSTR;
        uint4 pk;
        pk.x = pack_h2(y0,    y1[0]);
        pk.y = pack_h2(y1[1], y1[2]);
        pk.z = pack_h2(y2[0], y2[1]);
        pk.w = pack_h2(y2[2], y2[3]);
        *(uint4*)(yr + j * 8) = pk;
        yr[256 + j] = __float2half_rn(y2[4]);
        __syncwarp();
    }
}

// ---------------------------------------------------------------------------
// Kernel 2: edge conv — fp16 gathers + fp16 m16n8k16 MMA + fp32 SoA red
// ---------------------------------------------------------------------------
__device__ __forceinline__ void mma_f16(float& d0, float& d1, float& d2, float& d3,
                                        unsigned a0, unsigned a1, unsigned a2, unsigned a3,
                                        unsigned b0, unsigned b1)
{
    asm("mma.sync.aligned.m16n8k16.row.col.f32.f16.f16.f32 "
        "{%0,%1,%2,%3}, {%4,%5,%6,%7}, {%8,%9}, {%0,%1,%2,%3};"
        : "+f"(d0), "+f"(d1), "+f"(d2), "+f"(d3)
        : "r"(a0), "r"(a1), "r"(a2), "r"(a3), "r"(b0), "r"(b1));
}

__global__ void __launch_bounds__(256, 3) k_edge(
    const __half* __restrict__ si1, const float* __restrict__ pos,
    const int* __restrict__ edge_index,      // int32 (JAX x64 disabled)
    const float* __restrict__ Wr1, const float* __restrict__ br1,
    float* __restrict__ conv, int E)
{
    extern __shared__ char smraw[];
    __half* h16    = (__half*)smraw;                    // 64*72*2  = 9216
    __half* w16    = (__half*)(smraw + 9216);           // 64*232*2 = 29696
    float*  rbf_sm = (float*)(smraw + 38912);           // 8*64*4   = 2048
    float*  uy_sm  = (float*)(smraw + 40960);           // 64*8*4   = 2048
    int*    src_sm = (int*)(smraw + 43008);             // 256
    int*    dst_sm = (int*)(smraw + 43264);             // 256
    float*  Wr1s   = (float*)(smraw + 43520);           // 2048
    float*  br1s   = (float*)(smraw + 45568);           // 256  -> total 45824 B

    int t = threadIdx.x;
    for (int i = t; i < NRBF * HID; i += 256) Wr1s[i] = Wr1[i];
    if (t < HID) br1s[t] = br1[t];
    __syncthreads();

    const int j  = t & 31;   // lane
    const int g  = t >> 5;   // warp id (8 warps)
    const int e1 = t & 63;   // phase-1b edge within tile
    const int q  = t >> 6;   // phase-1b k-step (0..3), 16 k's each
    const int r4 = j >> 2;
    const int c4 = j & 3;
    const int msb = g & 1;   // phase-2 m-slab (32 edges)
    const int nq = g >> 1;   // phase-2 n-quarter (56 cols = 7 n8-tiles)
    const float rbf_step = 5.0f / 7.0f;

    const uint4* Bfrag = g_Bfrag16;

    int ntiles = (E + TILE_E - 1) / TILE_E;
    for (int tile = blockIdx.x; tile < ntiles; tile += gridDim.x) {
        int base = tile * TILE_E;

        // -------- phase 1a: geometry, once per edge (threads 0..63) --------
        if (t < TILE_E) {
            int eg = base + t;
            if (eg < E) {
                int s = edge_index[eg];
                int d = edge_index[(size_t)E + eg];
                float rx = pos[s*3+0] - pos[d*3+0];
                float ry = pos[s*3+1] - pos[d*3+1];
                float rz = pos[s*3+2] - pos[d*3+2];
                float dd = sqrtf(fmaf(rx,rx, fmaf(ry,ry, rz*rz)) + 1e-12f);
                float inv = 1.f / dd;
                float ux = rx*inv, uy = ry*inv, uz = rz*inv;
                #pragma unroll
                for (int r = 0; r < 8; r++) {
                    float dr = dd - rbf_step * (float)r;
                    rbf_sm[r*TILE_E + t] = __expf(-dr * dr);
                }
                float4* uv = (float4*)&uy_sm[t * 8];
                uv[0] = make_float4(ux, uy, uz, ux*uy);
                uv[1] = make_float4(uy*uz, (3.f*uz*uz - 1.f) * 0.2886751345948129f,
                                    ux*uz, (ux*ux - uy*uy) * 0.5f);
                src_sm[t] = s;
                dst_sm[t] = d;
            } else {
                #pragma unroll
                for (int r = 0; r < 8; r++) rbf_sm[r*TILE_E + t] = 0.f;
                float4* uv = (float4*)&uy_sm[t * 8];
                uv[0] = make_float4(0.f,0.f,0.f,0.f);
                uv[1] = make_float4(0.f,0.f,0.f,0.f);
                src_sm[t] = 0; dst_sm[t] = 0;
            }
        }
        __syncthreads();

        // -------- phase 1b: hidden layer h (fp16), vectorized --------
        {
            float rbf[8];
            #pragma unroll
            for (int r = 0; r < 8; r++) rbf[r] = rbf_sm[r*TILE_E + e1];

            float a[16];
            {
                const float4* bb = (const float4*)&br1s[q*16];
                #pragma unroll
                for (int v = 0; v < 4; v++) {
                    float4 b4 = bb[v];
                    a[4*v+0]=b4.x; a[4*v+1]=b4.y; a[4*v+2]=b4.z; a[4*v+3]=b4.w;
                }
            }
            #pragma unroll
            for (int r = 0; r < 8; r++) {
                const float4* wr = (const float4*)&Wr1s[r*HID + q*16];
                float rr = rbf[r];
                #pragma unroll
                for (int v = 0; v < 4; v++) {
                    float4 w4 = wr[v];
                    a[4*v+0] = fmaf(rr, w4.x, a[4*v+0]);
                    a[4*v+1] = fmaf(rr, w4.y, a[4*v+1]);
                    a[4*v+2] = fmaf(rr, w4.z, a[4*v+2]);
                    a[4*v+3] = fmaf(rr, w4.w, a[4*v+3]);
                }
            }
            // silu -> fp16, pack 16 halves = 2 uint4
            uint4 p0, p1;
            float s0 = a[0]/(1.f+__expf(-a[0])), s1 = a[1]/(1.f+__expf(-a[1]));
            float s2 = a[2]/(1.f+__expf(-a[2])), s3 = a[3]/(1.f+__expf(-a[3]));
            float s4 = a[4]/(1.f+__expf(-a[4])), s5 = a[5]/(1.f+__expf(-a[5]));
            float s6 = a[6]/(1.f+__expf(-a[6])), s7 = a[7]/(1.f+__expf(-a[7]));
            p0.x = pack_h2(s0,s1); p0.y = pack_h2(s2,s3);
            p0.z = pack_h2(s4,s5); p0.w = pack_h2(s6,s7);
            float s8 = a[8]/(1.f+__expf(-a[8])),  s9 = a[9]/(1.f+__expf(-a[9]));
            float sa = a[10]/(1.f+__expf(-a[10])), sb = a[11]/(1.f+__expf(-a[11]));
            float sc = a[12]/(1.f+__expf(-a[12])), sd = a[13]/(1.f+__expf(-a[13]));
            float se = a[14]/(1.f+__expf(-a[14])), sf = a[15]/(1.f+__expf(-a[15]));
            p1.x = pack_h2(s8,s9); p1.y = pack_h2(sa,sb);
            p1.z = pack_h2(sc,sd); p1.w = pack_h2(se,sf);
            *(uint4*)&h16[e1*HSTRH + q*16]     = p0;
            *(uint4*)&h16[e1*HSTRH + q*16 + 8] = p1;
        }
        __syncthreads();

        // -------- phase 2: w = h @ Wr2, fp16 m16n8k16, 2m x 4n split --------
        {
            float acc[2][7][4];
            #pragma unroll
            for (int mt = 0; mt < 2; mt++)
                #pragma unroll
                for (int nt = 0; nt < 7; nt++)
                    #pragma unroll
                    for (int i = 0; i < 4; i++) acc[mt][nt][i] = 0.f;

            #pragma unroll
            for (int kd = 0; kd < 2; kd++) {
                unsigned af[2][2][4];   // [mt][s][frag]
                #pragma unroll
                for (int mt = 0; mt < 2; mt++) {
                    int arow = msb*32 + mt*16 + r4;
                    #pragma unroll
                    for (int s = 0; s < 2; s++) {
                        int ko = (2*kd + s)*16 + 2*c4;
                        af[mt][s][0] = *(unsigned*)&h16[ arow    *HSTRH + ko    ];
                        af[mt][s][1] = *(unsigned*)&h16[(arow+8)*HSTRH + ko    ];
                        af[mt][s][2] = *(unsigned*)&h16[ arow    *HSTRH + ko + 8];
                        af[mt][s][3] = *(unsigned*)&h16[(arow+8)*HSTRH + ko + 8];
                    }
                }
                #pragma unroll
                for (int nt = 0; nt < 7; nt++) {
                    int ntg = nq*7 + nt;
                    uint4 b = __ldg(&Bfrag[(ntg*2 + kd)*32 + j]);
                    #pragma unroll
                    for (int mt = 0; mt < 2; mt++) {
                        mma_f16(acc[mt][nt][0], acc[mt][nt][1], acc[mt][nt][2], acc[mt][nt][3],
                                af[mt][0][0], af[mt][0][1], af[mt][0][2], af[mt][0][3],
                                b.x, b.y);
                        mma_f16(acc[mt][nt][0], acc[mt][nt][1], acc[mt][nt][2], acc[mt][nt][3],
                                af[mt][1][0], af[mt][1][1], af[mt][1][2], af[mt][1][3],
                                b.z, b.w);
                    }
                }
            }
            // epilogue: fp16 half2 stores (conflict-free with WSTRH=232)
            #pragma unroll
            for (int mt = 0; mt < 2; mt++) {
                #pragma unroll
                for (int nt = 0; nt < 7; nt++) {
                    int col = nq*56 + nt*8 + 2*c4;
                    int row = msb*32 + mt*16 + r4;
                    *(unsigned*)&w16[ row    *WSTRH + col] = pack_h2(acc[mt][nt][0], acc[mt][nt][1]);
                    *(unsigned*)&w16[(row+8)*WSTRH + col] = pack_h2(acc[mt][nt][2], acc[mt][nt][3]);
                }
            }
        }
        __syncthreads();

        // -------- phase 3: fp16 SoA gathers, compute, fp32 SoA red --------
        {
            const int ebase = g * 8;
            int nvalid = E - base - ebase;
            nvalid = nvalid < 0 ? 0 : (nvalid > 8 ? 8 : nvalid);
            if (nvalid > 0) {
                const __half* xp = si1 + (size_t)src_sm[ebase] * XSTR;
                uint4 pA = *(const uint4*)(xp + j*8);
                unsigned short pC = *(const unsigned short*)(xp + 256 + j);

                #pragma unroll
                for (int es = 0; es < 8; es++) {
                    if (es < nvalid) {
                        uint4 A = pA;
                        unsigned short Cc = pC;
                        if (es + 1 < nvalid) {
                            const __half* nx = si1 + (size_t)src_sm[ebase+es+1] * XSTR;
                            pA = *(const uint4*)(nx + j*8);
                            pC = *(const unsigned short*)(nx + 256 + j);
                        }
                        int e = ebase + es;
                        // decode fp16 -> fp32
                        float2 f0 = __half22float2(*(__half2*)&A.x);  // x0, x1[0]
                        float2 f1 = __half22float2(*(__half2*)&A.y);  // x1[1], x1[2]
                        float2 f2 = __half22float2(*(__half2*)&A.z);  // x2[0], x2[1]
                        float2 f3 = __half22float2(*(__half2*)&A.w);  // x2[2], x2[3]
                        float  C  = __half2float(*(__half*)&Cc);      // x2[4]

                        float w[7];
                        #pragma unroll
                        for (int p = 0; p < 7; p++)
                            w[p] = __half2float(w16[e*WSTRH + p*32 + j]);

                        float4 uy0 = *(float4*)&uy_sm[e*8];
                        float4 uy1 = *(float4*)&uy_sm[e*8 + 4];
                        // u = (uy0.x,y,z); Y2 = (uy0.w, uy1.x,y,z,w)

                        float x0 = f0.x;
                        float t1 = fmaf(f0.y, uy0.x, fmaf(f1.x, uy0.y, f1.y*uy0.z));
                        float t2 = f2.x*uy0.w;
                        t2 = fmaf(f2.y, uy1.x, t2);
                        t2 = fmaf(f3.x, uy1.y, t2);
                        t2 = fmaf(f3.y, uy1.z, t2);
                        t2 = fmaf(C,    uy1.w, t2);

                        float m0 = fmaf(w[0], x0, fmaf(w[4], t1, w[6]*t2));
                        float a3 = w[3] * x0;
                        float a5 = w[5] * x0;
                        float m1x = fmaf(w[1], f0.y, a3*uy0.x);
                        float m1y = fmaf(w[1], f1.x, a3*uy0.y);
                        float m1z = fmaf(w[1], f1.y, a3*uy0.z);
                        float m20 = fmaf(w[2], f2.x, a5*uy0.w);
                        float m21 = fmaf(w[2], f2.y, a5*uy1.x);
                        float m22 = fmaf(w[2], f3.x, a5*uy1.y);
                        float m23 = fmaf(w[2], f3.y, a5*uy1.z);
                        float m24 = fmaf(w[2], C,    a5*uy1.w);

                        float* db = conv + (size_t)dst_sm[e] * XSTR;
                        asm volatile("red.global.add.v4.f32 [%0], {%1,%2,%3,%4};"
                                     :: "l"(db + j*4), "f"(m0), "f"(m1x), "f"(m1y), "f"(m1z)
                                     : "memory");
                        asm volatile("red.global.add.v4.f32 [%0], {%1,%2,%3,%4};"
                                     :: "l"(db + 128 + j*4), "f"(m20), "f"(m21), "f"(m22), "f"(m23)
                                     : "memory");
                        asm volatile("red.global.add.f32 [%0], %1;"
                                     :: "l"(db + 256 + j), "f"(m24) : "memory");
                    }
                }
            }
        }
        __syncthreads();
    }
}

// ---------------------------------------------------------------------------
// Kernel 3: out = gate(nodes + irreps_linear(conv))   (conv read as fp32 SoA)
// ---------------------------------------------------------------------------
__global__ void k_lin2_gate(const float* __restrict__ conv,
                            const float* __restrict__ nodes,
                            const float* __restrict__ W0,
                            const float* __restrict__ W1,
                            const float* __restrict__ W2,
                            const float* __restrict__ Wg,
                            float* __restrict__ out, int N)
{
    __shared__ float W0s[1024], W1s[1024], W2s[1024], Wgs[2048];
    __shared__ float xs[8][DIM];
    __shared__ float m0s[8][32];
    int t = threadIdx.x;
    for (int i = t; i < 1024; i += blockDim.x) { W0s[i]=W0[i]; W1s[i]=W1[i]; W2s[i]=W2[i]; }
    for (int i = t; i < 2048; i += blockDim.x) Wgs[i] = Wg[i];
    __syncthreads();

    int wid = t >> 5, j = t & 31;
    int nwarps = (blockDim.x >> 5) * gridDim.x;
    for (int n = blockIdx.x * 8 + wid; n < N; n += nwarps) {
        const float* cr = conv + (size_t)n * XSTR;
        const float* nr = nodes + (size_t)n * DIM;
        {
            float4 cA = ((const float4*)cr)[j];
            float4 cB = ((const float4*)cr)[32 + j];
            float  cC = cr[256 + j];
            xs[wid][j] = cA.x;
            xs[wid][32 + 3*j + 0] = cA.y;
            xs[wid][32 + 3*j + 1] = cA.z;
            xs[wid][32 + 3*j + 2] = cA.w;
            xs[wid][128 + 5*j + 0] = cB.x;
            xs[wid][128 + 5*j + 1] = cB.y;
            xs[wid][128 + 5*j + 2] = cB.z;
            xs[wid][128 + 5*j + 3] = cB.w;
            xs[wid][128 + 5*j + 4] = cC;
        }
        __syncwarp();

        float y0 = nr[j];
        #pragma unroll
        for (int i = 0; i < 32; i++) y0 = fmaf(xs[wid][i], W0s[i*32+j], y0);
        m0s[wid][j] = y0;
        __syncwarp();

        float ga = 0.f, gb = 0.f;
        #pragma unroll
        for (int i = 0; i < 32; i++) {
            float mi = m0s[wid][i];
            ga = fmaf(mi, Wgs[i*64 + j],      ga);
            gb = fmaf(mi, Wgs[i*64 + 32 + j], gb);
        }
        ga = 1.f / (1.f + __expf(-ga));
        gb = 1.f / (1.f + __expf(-gb));

        float y1[3];
        #pragma unroll
        for (int c = 0; c < 3; c++) y1[c] = nr[32 + 3*j + c];
        #pragma unroll
        for (int i = 0; i < 32; i++) {
            float w = W1s[i*32+j];
            #pragma unroll
            for (int c = 0; c < 3; c++) y1[c] = fmaf(xs[wid][32+3*i+c], w, y1[c]);
        }
        float y2[5];
        #pragma unroll
        for (int c = 0; c < 5; c++) y2[c] = nr[128 + 5*j + c];
        #pragma unroll
        for (int i = 0; i < 32; i++) {
            float w = W2s[i*32+j];
            #pragma unroll
            for (int c = 0; c < 5; c++) y2[c] = fmaf(xs[wid][128+5*i+c], w, y2[c]);
        }

        float* yr = out + (size_t)n * DIM;
        yr[j] = y0 / (1.f + __expf(-y0));     // silu
        #pragma unroll
        for (int c = 0; c < 3; c++) yr[32 + 3*j + c] = y1[c] * ga;
        #pragma unroll
        for (int c = 0; c < 5; c++) yr[128 + 5*j + c] = y2[c] * gb;
        __syncwarp();
    }
}

// ---------------------------------------------------------------------------
extern "C" void kernel_launch(void* const* d_in, const int* in_sizes, int n_in,
                              void* d_out, int out_size)
{
    const float* nodes = (const float*)d_in[0];
    const float* pos   = (const float*)d_in[1];
    const float* W0    = (const float*)d_in[2];
    const float* W1    = (const float*)d_in[3];
    const float* W2    = (const float*)d_in[4];
    const float* Wr1   = (const float*)d_in[5];
    const float* br1   = (const float*)d_in[6];
    const float* Wr2   = (const float*)d_in[7];
    const float* Wg    = (const float*)d_in[8];
    const int* edge_index = (const int*)d_in[10];   // int32: JAX x64 disabled
    float* out = (float*)d_out;

    int N = in_sizes[0] / DIM;
    int E = in_sizes[10] / 2;

    __half* si1p;
    float* convp;
    cudaGetSymbolAddress((void**)&si1p, g_si1h);
    cudaGetSymbolAddress((void**)&convp, g_conv);

    int nblocks = (N + 7) / 8;
    if (nblocks > 2048) nblocks = 2048;

    k_prep<<<28, 64>>>(Wr2);                                        // kernel 0
    k_lin1<<<nblocks, 256>>>(nodes, W0, W1, W2, si1p, convp, N);    // kernel 1
    k_prep<<<28, 64>>>(Wr2);    // idempotent dummy — keeps k_edge at idx 3

    const int SMEM = 45824;     // bytes; 3 blocks/SM fit easily
    cudaFuncSetAttribute(k_edge, cudaFuncAttributeMaxDynamicSharedMemorySize, SMEM);
    k_edge<<<888, 256, SMEM>>>(si1p, pos, edge_index, Wr1, br1, convp, E);  // kernel 3

    k_lin2_gate<<<nblocks, 256>>>(convp, nodes, W0, W1, W2, Wg, out, N);    // kernel 4
}